// round 1
// baseline (speedup 1.0000x reference)
#include <cuda_runtime.h>
#include <math.h>

#define B_ 4
#define T_ 2048
#define C_ 2048
#define H_ 16
#define D_ 128
#define L_ 512
#define BT_ (B_*T_)

// ---------------- scratch (device globals; no allocation allowed) ----------------
__device__ float g_q[(size_t)BT_ * H_ * D_];   // 64 MB
__device__ float g_lat[(size_t)BT_ * L_];      // 16 MB
__device__ float g_k[(size_t)BT_ * D_];        // 4 MB
__device__ float g_v[(size_t)BT_ * D_];        // 4 MB
__device__ float g_y[(size_t)BT_ * H_ * D_];   // 64 MB

// ---------------- generic NT SGEMM: C[M,N] = A[M,K] * B[N,K]^T ----------------
// Requires M%128==0, N%128==0, K%8==0 (all shapes here satisfy this).
__global__ __launch_bounds__(256) void sgemm_nt(
    const float* __restrict__ A, const float* __restrict__ Bm,
    float* __restrict__ Cm, int M, int N, int K)
{
    __shared__ float As[8][128];
    __shared__ float Bs[8][128];
    const int tid  = threadIdx.x;
    const int tx   = tid & 15;
    const int ty   = tid >> 4;
    const int lrow = tid >> 1;          // 0..127
    const int lcol = (tid & 1) << 2;    // 0 or 4

    const float* Ab = A  + (size_t)blockIdx.y * 128 * K;
    const float* Bb = Bm + (size_t)blockIdx.x * 128 * K;

    float acc[8][8];
#pragma unroll
    for (int i = 0; i < 8; i++)
#pragma unroll
        for (int j = 0; j < 8; j++) acc[i][j] = 0.f;

    for (int k0 = 0; k0 < K; k0 += 8) {
        float4 av = *(const float4*)(Ab + (size_t)lrow * K + k0 + lcol);
        float4 bv = *(const float4*)(Bb + (size_t)lrow * K + k0 + lcol);
        As[lcol + 0][lrow] = av.x; As[lcol + 1][lrow] = av.y;
        As[lcol + 2][lrow] = av.z; As[lcol + 3][lrow] = av.w;
        Bs[lcol + 0][lrow] = bv.x; Bs[lcol + 1][lrow] = bv.y;
        Bs[lcol + 2][lrow] = bv.z; Bs[lcol + 3][lrow] = bv.w;
        __syncthreads();
#pragma unroll
        for (int kk = 0; kk < 8; kk++) {
            float a[8], b[8];
            *(float4*)&a[0] = *(const float4*)&As[kk][ty * 8];
            *(float4*)&a[4] = *(const float4*)&As[kk][ty * 8 + 4];
            *(float4*)&b[0] = *(const float4*)&Bs[kk][tx * 8];
            *(float4*)&b[4] = *(const float4*)&Bs[kk][tx * 8 + 4];
#pragma unroll
            for (int i = 0; i < 8; i++)
#pragma unroll
                for (int j = 0; j < 8; j++)
                    acc[i][j] += a[i] * b[j];
        }
        __syncthreads();
    }

    const int row0 = blockIdx.y * 128 + ty * 8;
    const int col0 = blockIdx.x * 128 + tx * 8;
#pragma unroll
    for (int i = 0; i < 8; i++) {
        *(float4*)(Cm + (size_t)(row0 + i) * N + col0) =
            make_float4(acc[i][0], acc[i][1], acc[i][2], acc[i][3]);
        *(float4*)(Cm + (size_t)(row0 + i) * N + col0 + 4) =
            make_float4(acc[i][4], acc[i][5], acc[i][6], acc[i][7]);
    }
}

// ---------------- RoPE (interleaved pairs) ----------------
// q layout [B,T,H,D]; pair j uses cos/sin[t, j], j in [0,64)
__global__ void rope_q_kernel(float* __restrict__ q,
                              const float* __restrict__ cs,
                              const float* __restrict__ sn)
{
    int idx = blockIdx.x * blockDim.x + threadIdx.x;   // over B*T*H*64
    int j = idx & 63;
    int t = (idx >> 10) & (T_ - 1);                    // 64*H = 1024
    float c = cs[t * 64 + j];
    float s = sn[t * 64 + j];
    float2 v = *(float2*)(q + (size_t)idx * 2);
    *(float2*)(q + (size_t)idx * 2) = make_float2(v.x * c - v.y * s,
                                                  v.x * s + v.y * c);
}

// k layout [B,T,D]
__global__ void rope_k_kernel(float* __restrict__ k,
                              const float* __restrict__ cs,
                              const float* __restrict__ sn)
{
    int idx = blockIdx.x * blockDim.x + threadIdx.x;   // over B*T*64
    int j = idx & 63;
    int t = (idx >> 6) & (T_ - 1);
    float c = cs[t * 64 + j];
    float s = sn[t * 64 + j];
    float2 v = *(float2*)(k + (size_t)idx * 2);
    *(float2*)(k + (size_t)idx * 2) = make_float2(v.x * c - v.y * s,
                                                  v.x * s + v.y * c);
}

// ---------------- causal flash attention (single KV head, fp32) ----------------
#define BR 64
#define BC 64
#define ST_STRIDE 68  // 64 + 4: keeps float4 alignment and spreads banks
#define ATTN_SMEM_BYTES ((128*64 + 128*64 + 64*128 + 64*ST_STRIDE + 192) * 4)

__global__ __launch_bounds__(256) void attn_kernel(
    const float* __restrict__ gq, const float* __restrict__ gk,
    const float* __restrict__ gv, float* __restrict__ gy)
{
    extern __shared__ float sm[];
    float* Qt  = sm;                    // [128][64]  Qt[k][r]
    float* Kt  = Qt + 128 * 64;         // [128][64]  Kt[k][c]
    float* Vs  = Kt + 128 * 64;         // [64][128]  Vs[c][d]
    float* St  = Vs + 64 * 128;         // [64][ST_STRIDE]  St[c][r]
    float* m_s  = St + 64 * ST_STRIDE;  // [64]
    float* l_s  = m_s + 64;             // [64]
    float* sc_s = l_s + 64;             // [64]

    const int tid = threadIdx.x;        // 256
    const int qt = blockIdx.x, h = blockIdx.y, b = blockIdx.z;
    const int t0 = qt * BR;
    const int tx = tid & 15;
    const int ty = tid >> 4;
    const int rb = ty * 4;              // 4 rows per thread
    const int cb = tx * 4;              // 4(+4) cols per thread
    const float scale = 0.08838834764831845f;   // 1/sqrt(128)

    // load Q tile transposed: Qt[d][r]
    const float* qbase = gq + (((size_t)b * T_ + t0) * H_ + h) * D_;
#pragma unroll
    for (int it = 0; it < 8; it++) {
        int i  = tid + 256 * it;        // 0..2047 float4s
        int r  = i & 63;
        int dq = (i >> 6) << 2;
        float4 v4 = *(const float4*)(qbase + (size_t)r * (H_ * D_) + dq);
        Qt[(dq + 0) * 64 + r] = v4.x; Qt[(dq + 1) * 64 + r] = v4.y;
        Qt[(dq + 2) * 64 + r] = v4.z; Qt[(dq + 3) * 64 + r] = v4.w;
    }
    if (tid < 64) { m_s[tid] = -3.4e38f; l_s[tid] = 0.f; }

    float o[4][8];
#pragma unroll
    for (int i = 0; i < 4; i++)
#pragma unroll
        for (int j = 0; j < 8; j++) o[i][j] = 0.f;

    for (int j = 0; j <= qt; j++) {
        __syncthreads();   // prior-iter consumers done before overwriting Kt/Vs
        const float* kbase = gk + ((size_t)b * T_ + j * BC) * D_;
        const float* vbase = gv + ((size_t)b * T_ + j * BC) * D_;
#pragma unroll
        for (int it = 0; it < 8; it++) {
            int i  = tid + 256 * it;
            int r  = i & 63;
            int dq = (i >> 6) << 2;
            float4 k4 = *(const float4*)(kbase + (size_t)r * D_ + dq);
            Kt[(dq + 0) * 64 + r] = k4.x; Kt[(dq + 1) * 64 + r] = k4.y;
            Kt[(dq + 2) * 64 + r] = k4.z; Kt[(dq + 3) * 64 + r] = k4.w;
            int rv = i >> 5;
            int dv = (i & 31) << 2;
            *(float4*)&Vs[rv * 128 + dv] =
                *(const float4*)(vbase + (size_t)rv * D_ + dv);
        }
        __syncthreads();

        // S = scale * Q K^T  (4x4 per thread), write transposed into St[c][r]
        float s4[4][4];
#pragma unroll
        for (int ii = 0; ii < 4; ii++)
#pragma unroll
            for (int jj = 0; jj < 4; jj++) s4[ii][jj] = 0.f;

        for (int k = 0; k < 128; k++) {
            float4 qf = *(const float4*)&Qt[k * 64 + rb];
            float4 kf = *(const float4*)&Kt[k * 64 + cb];
            float qa[4] = {qf.x, qf.y, qf.z, qf.w};
            float ka[4] = {kf.x, kf.y, kf.z, kf.w};
#pragma unroll
            for (int ii = 0; ii < 4; ii++)
#pragma unroll
                for (int jj = 0; jj < 4; jj++)
                    s4[ii][jj] += qa[ii] * ka[jj];
        }
        const bool diag = (j == qt);
#pragma unroll
        for (int ii = 0; ii < 4; ii++)
#pragma unroll
            for (int jj = 0; jj < 4; jj++) {
                float val = s4[ii][jj] * scale;
                if (diag && (j * BC + cb + jj) > (t0 + rb + ii)) val = -3.0e38f;
                St[(cb + jj) * ST_STRIDE + rb + ii] = val;
            }
        __syncthreads();

        // online softmax per row (64 rows, 64 threads)
        if (tid < 64) {
            int r = tid;
            float mx = -3.4e38f;
#pragma unroll 8
            for (int c = 0; c < 64; c++) mx = fmaxf(mx, St[c * ST_STRIDE + r]);
            float mold = m_s[r];
            float mnew = fmaxf(mold, mx);
            float sc   = __expf(mold - mnew);
            float sum  = 0.f;
#pragma unroll 8
            for (int c = 0; c < 64; c++) {
                float p = __expf(St[c * ST_STRIDE + r] - mnew);
                St[c * ST_STRIDE + r] = p;
                sum += p;
            }
            m_s[r]  = mnew;
            l_s[r]  = l_s[r] * sc + sum;
            sc_s[r] = sc;
        }
        __syncthreads();

        // rescale accumulator, then O += P @ V
        float scl[4];
#pragma unroll
        for (int ii = 0; ii < 4; ii++) scl[ii] = sc_s[rb + ii];
#pragma unroll
        for (int ii = 0; ii < 4; ii++)
#pragma unroll
            for (int jj = 0; jj < 8; jj++) o[ii][jj] *= scl[ii];

        for (int c = 0; c < 64; c++) {
            float4 pf = *(const float4*)&St[c * ST_STRIDE + rb];
            float pa[4] = {pf.x, pf.y, pf.z, pf.w};
            float4 v0 = *(const float4*)&Vs[c * 128 + cb];
            float4 v1 = *(const float4*)&Vs[c * 128 + 64 + cb];
            float va[8] = {v0.x, v0.y, v0.z, v0.w, v1.x, v1.y, v1.z, v1.w};
#pragma unroll
            for (int ii = 0; ii < 4; ii++)
#pragma unroll
                for (int jj = 0; jj < 8; jj++)
                    o[ii][jj] += pa[ii] * va[jj];
        }
    }

    // epilogue: divide by l, store to y [B,T,H,D]
    float* ybase = gy + (((size_t)b * T_ + t0) * H_ + h) * D_;
#pragma unroll
    for (int ii = 0; ii < 4; ii++) {
        float inv = 1.f / l_s[rb + ii];
        *(float4*)(ybase + (size_t)(rb + ii) * (H_ * D_) + cb) =
            make_float4(o[ii][0] * inv, o[ii][1] * inv, o[ii][2] * inv, o[ii][3] * inv);
        *(float4*)(ybase + (size_t)(rb + ii) * (H_ * D_) + 64 + cb) =
            make_float4(o[ii][4] * inv, o[ii][5] * inv, o[ii][6] * inv, o[ii][7] * inv);
    }
}

// ---------------- host launcher ----------------
extern "C" void kernel_launch(void* const* d_in, const int* in_sizes, int n_in,
                              void* d_out, int out_size)
{
    const float* x     = (const float*)d_in[0];
    const float* fcos  = (const float*)d_in[1];
    const float* fsin  = (const float*)d_in[2];
    const float* wq    = (const float*)d_in[3];
    const float* wkv   = (const float*)d_in[4];
    const float* wk_up = (const float*)d_in[5];
    const float* wv_up = (const float*)d_in[6];
    const float* wo    = (const float*)d_in[7];
    float* out = (float*)d_out;

    float *pq, *plat, *pk, *pv, *py;
    cudaGetSymbolAddress((void**)&pq,   g_q);
    cudaGetSymbolAddress((void**)&plat, g_lat);
    cudaGetSymbolAddress((void**)&pk,   g_k);
    cudaGetSymbolAddress((void**)&pv,   g_v);
    cudaGetSymbolAddress((void**)&py,   g_y);
    cudaFuncSetAttribute(attn_kernel,
                         cudaFuncAttributeMaxDynamicSharedMemorySize,
                         ATTN_SMEM_BYTES);

    dim3 thr(256);
    // q = x @ wq^T        [8192 x 2048 x 2048]
    sgemm_nt<<<dim3((H_ * D_) / 128, BT_ / 128), thr>>>(x, wq, pq, BT_, H_ * D_, C_);
    // lat = x @ wkv^T     [8192 x 512 x 2048]
    sgemm_nt<<<dim3(L_ / 128, BT_ / 128), thr>>>(x, wkv, plat, BT_, L_, C_);
    // k = lat @ wk_up^T   [8192 x 128 x 512]
    sgemm_nt<<<dim3(D_ / 128, BT_ / 128), thr>>>(plat, wk_up, pk, BT_, D_, L_);
    // v = lat @ wv_up^T
    sgemm_nt<<<dim3(D_ / 128, BT_ / 128), thr>>>(plat, wv_up, pv, BT_, D_, L_);
    // RoPE
    rope_q_kernel<<<(BT_ * H_ * 64) / 256, 256>>>(pq, fcos, fsin);
    rope_k_kernel<<<(BT_ * 64) / 256, 256>>>(pk, fcos, fsin);
    // attention
    attn_kernel<<<dim3(T_ / BR, H_, B_), 256, ATTN_SMEM_BYTES>>>(pq, pk, pv, py);
    // out = y @ wo^T      [8192 x 2048 x 2048]
    sgemm_nt<<<dim3(C_ / 128, BT_ / 128), thr>>>(py, wo, out, BT_, C_, H_ * D_);
}

// round 3
// speedup vs baseline: 1.5859x; 1.5859x over previous
#include <cuda_runtime.h>
#include <cuda_bf16.h>
#include <math.h>
#include <stdint.h>

#define B_ 4
#define T_ 2048
#define C_ 2048
#define H_ 16
#define D_ 128
#define L_ 512
#define BT_ (B_*T_)

// ---------------- fp32 scratch ----------------
__device__ float g_q[(size_t)BT_ * H_ * D_];
__device__ float g_lat[(size_t)BT_ * L_];
__device__ float g_k[(size_t)BT_ * D_];
__device__ float g_v[(size_t)BT_ * D_];
__device__ float g_y[(size_t)BT_ * H_ * D_];

// ---------------- bf16 hi/lo split scratch ----------------
__device__ __nv_bfloat16 g_xhi[(size_t)BT_ * C_];
__device__ __nv_bfloat16 g_xlo[(size_t)BT_ * C_];
__device__ __nv_bfloat16 g_lhi[(size_t)BT_ * L_];
__device__ __nv_bfloat16 g_llo[(size_t)BT_ * L_];
__device__ __nv_bfloat16 g_wqhi[(size_t)H_*D_*C_], g_wqlo[(size_t)H_*D_*C_];
__device__ __nv_bfloat16 g_wkvhi[(size_t)L_*C_],   g_wkvlo[(size_t)L_*C_];
__device__ __nv_bfloat16 g_wkuhi[(size_t)D_*L_],   g_wkulo[(size_t)D_*L_];
__device__ __nv_bfloat16 g_wvuhi[(size_t)D_*L_],   g_wvulo[(size_t)D_*L_];
__device__ __nv_bfloat16 g_wohi[(size_t)C_*H_*D_], g_wolo[(size_t)C_*H_*D_];

// ---------------- helpers ----------------
__device__ __forceinline__ uint32_t smem_u32(const void* p) {
    uint32_t a;
    asm("{ .reg .u64 t; cvta.to.shared.u64 t, %1; cvt.u32.u64 %0, t; }"
        : "=r"(a) : "l"(p));
    return a;
}
__device__ __forceinline__ void cp_async16(uint32_t dst, const void* src) {
    asm volatile("cp.async.cg.shared.global [%0], [%1], 16;"
                 :: "r"(dst), "l"(src) : "memory");
}
#define CP_COMMIT() asm volatile("cp.async.commit_group;" ::: "memory")
#define CP_WAIT1()  asm volatile("cp.async.wait_group 1;" ::: "memory")

__device__ __forceinline__ void ldm_x4(uint32_t& r0, uint32_t& r1,
                                       uint32_t& r2, uint32_t& r3, uint32_t a) {
    asm volatile("ldmatrix.sync.aligned.m8n8.x4.shared.b16 {%0,%1,%2,%3}, [%4];"
                 : "=r"(r0), "=r"(r1), "=r"(r2), "=r"(r3) : "r"(a));
}
__device__ __forceinline__ void mma16816(float* d, const uint32_t* a,
                                         uint32_t b0, uint32_t b1) {
    asm volatile(
        "mma.sync.aligned.m16n8k16.row.col.f32.bf16.bf16.f32 "
        "{%0,%1,%2,%3}, {%4,%5,%6,%7}, {%8,%9}, {%0,%1,%2,%3};"
        : "+f"(d[0]), "+f"(d[1]), "+f"(d[2]), "+f"(d[3])
        : "r"(a[0]), "r"(a[1]), "r"(a[2]), "r"(a[3]), "r"(b0), "r"(b1));
}

// ---------------- fp32 -> (hi,lo) bf16 split ----------------
__global__ void cvt_split(const float* __restrict__ s,
                          __nv_bfloat16* __restrict__ hi,
                          __nv_bfloat16* __restrict__ lo, int n4)
{
    int i = blockIdx.x * blockDim.x + threadIdx.x;
    if (i >= n4) return;
    float4 v = *(const float4*)(s + (size_t)i * 4);
    __nv_bfloat16 h0 = __float2bfloat16(v.x);
    __nv_bfloat16 h1 = __float2bfloat16(v.y);
    __nv_bfloat16 h2 = __float2bfloat16(v.z);
    __nv_bfloat16 h3 = __float2bfloat16(v.w);
    __nv_bfloat16 l0 = __float2bfloat16(v.x - __bfloat162float(h0));
    __nv_bfloat16 l1 = __float2bfloat16(v.y - __bfloat162float(h1));
    __nv_bfloat16 l2 = __float2bfloat16(v.z - __bfloat162float(h2));
    __nv_bfloat16 l3 = __float2bfloat16(v.w - __bfloat162float(h3));
    *(__nv_bfloat162*)(hi + (size_t)i * 4)     = __nv_bfloat162(h0, h1);
    *(__nv_bfloat162*)(hi + (size_t)i * 4 + 2) = __nv_bfloat162(h2, h3);
    *(__nv_bfloat162*)(lo + (size_t)i * 4)     = __nv_bfloat162(l0, l1);
    *(__nv_bfloat162*)(lo + (size_t)i * 4 + 2) = __nv_bfloat162(l2, l3);
}

// ---------------- mma.sync GEMM: C[M,N] = A*B^T, 3-term bf16 split ----------------
// A[M,K], B[N,K] row-major bf16 (hi/lo). Grid (N/128, M/128), 256 threads.
// SMEM tile: 128 rows x 32 bf16 (64 B rows), 16B chunks swizzled c^=(row>>1)&3.
#define GBK 32
#define GSTG 3
#define GTB 8192                    // bytes per tile stage
#define GM_SMEM (2 * GSTG * GTB)

__global__ __launch_bounds__(256, 2) void gemm_bf16x3(
    const __nv_bfloat16* __restrict__ Ahi, const __nv_bfloat16* __restrict__ Alo,
    const __nv_bfloat16* __restrict__ Bhi, const __nv_bfloat16* __restrict__ Blo,
    float* __restrict__ Cm, int N, int K)
{
    extern __shared__ char smraw[];
    const uint32_t sA = smem_u32(smraw);
    const uint32_t sB = sA + GSTG * GTB;

    const int tid  = threadIdx.x;
    const int wid  = tid >> 5;
    const int lane = tid & 31;
    const int wm = wid >> 2;            // 0..1
    const int wn = wid & 3;             // 0..3
    const int n0 = blockIdx.x * 128;
    const int m0 = blockIdx.y * 128;

    const int KB = K / GBK;
    const int total = 3 * KB;

    float acc[4][4][4];
#pragma unroll
    for (int i = 0; i < 4; i++)
#pragma unroll
        for (int j = 0; j < 4; j++)
#pragma unroll
            for (int u = 0; u < 4; u++) acc[i][j][u] = 0.f;

    auto load_stage = [&](int j, int s) {
        const int p  = j / KB;
        const int kc = j - p * KB;
        const __nv_bfloat16* A  = (p == 2) ? Alo : Ahi;
        const __nv_bfloat16* Bp = (p == 1) ? Blo : Bhi;
        const uint32_t as = sA + (uint32_t)s * GTB;
        const uint32_t bs = sB + (uint32_t)s * GTB;
#pragma unroll
        for (int i = 0; i < 2; i++) {
            int ch  = tid + i * 256;            // 0..511
            int row = ch >> 2;
            int c   = ch & 3;
            int csw = c ^ ((row >> 1) & 3);
            uint32_t off = (uint32_t)(row * 64 + csw * 16);
            cp_async16(as + off, A  + (size_t)(m0 + row) * K + kc * GBK + c * 8);
            cp_async16(bs + off, Bp + (size_t)(n0 + row) * K + kc * GBK + c * 8);
        }
    };

    load_stage(0, 0); CP_COMMIT();
    load_stage(1, 1); CP_COMMIT();

    for (int j = 0; j < total; j++) {
        const int s = j % GSTG;
        CP_WAIT1();
        __syncthreads();
        if (j + 2 < total) load_stage(j + 2, (j + 2) % GSTG);
        CP_COMMIT();

        const uint32_t as = sA + (uint32_t)s * GTB;
        const uint32_t bs = sB + (uint32_t)s * GTB;
#pragma unroll
        for (int kk = 0; kk < 2; kk++) {
            uint32_t a[4][4], b[2][4];
#pragma unroll
            for (int mt = 0; mt < 4; mt++) {
                int row = wm * 64 + mt * 16 + (lane & 15);
                int cc  = kk * 2 + (lane >> 4);
                int csw = cc ^ ((row >> 1) & 3);
                ldm_x4(a[mt][0], a[mt][1], a[mt][2], a[mt][3],
                       as + (uint32_t)(row * 64 + csw * 16));
            }
#pragma unroll
            for (int np = 0; np < 2; np++) {
                int row = wn * 32 + np * 16 + (lane & 15);
                int cc  = kk * 2 + (lane >> 4);
                int csw = cc ^ ((row >> 1) & 3);
                ldm_x4(b[np][0], b[np][1], b[np][2], b[np][3],
                       bs + (uint32_t)(row * 64 + csw * 16));
            }
#pragma unroll
            for (int mt = 0; mt < 4; mt++)
#pragma unroll
                for (int nt = 0; nt < 4; nt++)
                    mma16816(acc[mt][nt], a[mt],
                             b[nt >> 1][nt & 1], b[nt >> 1][(nt & 1) + 2]);
        }
        __syncthreads();
    }

    // epilogue: fragment rows (lane>>2, +8), cols (lane&3)*2, +1
    const int r0g = m0 + wm * 64 + (lane >> 2);
    const int c0g = n0 + wn * 32 + (lane & 3) * 2;
#pragma unroll
    for (int mt = 0; mt < 4; mt++)
#pragma unroll
        for (int nt = 0; nt < 4; nt++) {
            float* p0 = Cm + (size_t)(r0g + mt * 16) * N + c0g + nt * 8;
            *(float2*)p0                    = make_float2(acc[mt][nt][0], acc[mt][nt][1]);
            *(float2*)(p0 + (size_t)8 * N)  = make_float2(acc[mt][nt][2], acc[mt][nt][3]);
        }
}

// ---------------- RoPE (interleaved pairs) ----------------
__global__ void rope_q_kernel(float* __restrict__ q,
                              const float* __restrict__ cs,
                              const float* __restrict__ sn)
{
    int idx = blockIdx.x * blockDim.x + threadIdx.x;
    int j = idx & 63;
    int t = (idx >> 10) & (T_ - 1);
    float c = cs[t * 64 + j];
    float s = sn[t * 64 + j];
    float2 v = *(float2*)(q + (size_t)idx * 2);
    *(float2*)(q + (size_t)idx * 2) = make_float2(v.x * c - v.y * s,
                                                  v.x * s + v.y * c);
}
__global__ void rope_k_kernel(float* __restrict__ k,
                              const float* __restrict__ cs,
                              const float* __restrict__ sn)
{
    int idx = blockIdx.x * blockDim.x + threadIdx.x;
    int j = idx & 63;
    int t = (idx >> 6) & (T_ - 1);
    float c = cs[t * 64 + j];
    float s = sn[t * 64 + j];
    float2 v = *(float2*)(k + (size_t)idx * 2);
    *(float2*)(k + (size_t)idx * 2) = make_float2(v.x * c - v.y * s,
                                                  v.x * s + v.y * c);
}

// ---------------- causal flash attention (single KV head, fp32 SIMT) ----------------
#define BR 64
#define BC 64
#define ST_STRIDE 68
#define ATTN_SMEM_BYTES ((128*64 + 128*64 + 64*128 + 64*ST_STRIDE + 192) * 4)

__global__ __launch_bounds__(256) void attn_kernel(
    const float* __restrict__ gq, const float* __restrict__ gk,
    const float* __restrict__ gv, float* __restrict__ gy)
{
    extern __shared__ float sm[];
    float* Qt  = sm;
    float* Kt  = Qt + 128 * 64;
    float* Vs  = Kt + 128 * 64;
    float* St  = Vs + 64 * 128;
    float* m_s  = St + 64 * ST_STRIDE;
    float* l_s  = m_s + 64;
    float* sc_s = l_s + 64;

    const int tid = threadIdx.x;
    const int qt = blockIdx.x, h = blockIdx.y, b = blockIdx.z;
    const int t0 = qt * BR;
    const int tx = tid & 15;
    const int ty = tid >> 4;
    const int rb = ty * 4;
    const int cb = tx * 4;
    const float scale = 0.08838834764831845f;

    const float* qbase = gq + (((size_t)b * T_ + t0) * H_ + h) * D_;
#pragma unroll
    for (int it = 0; it < 8; it++) {
        int i  = tid + 256 * it;
        int r  = i & 63;
        int dq = (i >> 6) << 2;
        float4 v4 = *(const float4*)(qbase + (size_t)r * (H_ * D_) + dq);
        Qt[(dq + 0) * 64 + r] = v4.x; Qt[(dq + 1) * 64 + r] = v4.y;
        Qt[(dq + 2) * 64 + r] = v4.z; Qt[(dq + 3) * 64 + r] = v4.w;
    }
    if (tid < 64) { m_s[tid] = -3.4e38f; l_s[tid] = 0.f; }

    float o[4][8];
#pragma unroll
    for (int i = 0; i < 4; i++)
#pragma unroll
        for (int j = 0; j < 8; j++) o[i][j] = 0.f;

    for (int j = 0; j <= qt; j++) {
        __syncthreads();
        const float* kbase = gk + ((size_t)b * T_ + j * BC) * D_;
        const float* vbase = gv + ((size_t)b * T_ + j * BC) * D_;
#pragma unroll
        for (int it = 0; it < 8; it++) {
            int i  = tid + 256 * it;
            int r  = i & 63;
            int dq = (i >> 6) << 2;
            float4 k4 = *(const float4*)(kbase + (size_t)r * D_ + dq);
            Kt[(dq + 0) * 64 + r] = k4.x; Kt[(dq + 1) * 64 + r] = k4.y;
            Kt[(dq + 2) * 64 + r] = k4.z; Kt[(dq + 3) * 64 + r] = k4.w;
            int rv = i >> 5;
            int dv = (i & 31) << 2;
            *(float4*)&Vs[rv * 128 + dv] =
                *(const float4*)(vbase + (size_t)rv * D_ + dv);
        }
        __syncthreads();

        float s4[4][4];
#pragma unroll
        for (int ii = 0; ii < 4; ii++)
#pragma unroll
            for (int jj = 0; jj < 4; jj++) s4[ii][jj] = 0.f;

        for (int k = 0; k < 128; k++) {
            float4 qf = *(const float4*)&Qt[k * 64 + rb];
            float4 kf = *(const float4*)&Kt[k * 64 + cb];
            float qa[4] = {qf.x, qf.y, qf.z, qf.w};
            float ka[4] = {kf.x, kf.y, kf.z, kf.w};
#pragma unroll
            for (int ii = 0; ii < 4; ii++)
#pragma unroll
                for (int jj = 0; jj < 4; jj++)
                    s4[ii][jj] += qa[ii] * ka[jj];
        }
        const bool diag = (j == qt);
#pragma unroll
        for (int ii = 0; ii < 4; ii++)
#pragma unroll
            for (int jj = 0; jj < 4; jj++) {
                float val = s4[ii][jj] * scale;
                if (diag && (j * BC + cb + jj) > (t0 + rb + ii)) val = -3.0e38f;
                St[(cb + jj) * ST_STRIDE + rb + ii] = val;
            }
        __syncthreads();

        if (tid < 64) {
            int r = tid;
            float mx = -3.4e38f;
#pragma unroll 8
            for (int c = 0; c < 64; c++) mx = fmaxf(mx, St[c * ST_STRIDE + r]);
            float mold = m_s[r];
            float mnew = fmaxf(mold, mx);
            float sc   = __expf(mold - mnew);
            float sum  = 0.f;
#pragma unroll 8
            for (int c = 0; c < 64; c++) {
                float p = __expf(St[c * ST_STRIDE + r] - mnew);
                St[c * ST_STRIDE + r] = p;
                sum += p;
            }
            m_s[r]  = mnew;
            l_s[r]  = l_s[r] * sc + sum;
            sc_s[r] = sc;
        }
        __syncthreads();

        float scl[4];
#pragma unroll
        for (int ii = 0; ii < 4; ii++) scl[ii] = sc_s[rb + ii];
#pragma unroll
        for (int ii = 0; ii < 4; ii++)
#pragma unroll
            for (int jj = 0; jj < 8; jj++) o[ii][jj] *= scl[ii];

        for (int c = 0; c < 64; c++) {
            float4 pf = *(const float4*)&St[c * ST_STRIDE + rb];
            float pa[4] = {pf.x, pf.y, pf.z, pf.w};
            float4 v0 = *(const float4*)&Vs[c * 128 + cb];
            float4 v1 = *(const float4*)&Vs[c * 128 + 64 + cb];
            float va[8] = {v0.x, v0.y, v0.z, v0.w, v1.x, v1.y, v1.z, v1.w};
#pragma unroll
            for (int ii = 0; ii < 4; ii++)
#pragma unroll
                for (int jj = 0; jj < 8; jj++)
                    o[ii][jj] += pa[ii] * va[jj];
        }
    }

    float* ybase = gy + (((size_t)b * T_ + t0) * H_ + h) * D_;
#pragma unroll
    for (int ii = 0; ii < 4; ii++) {
        float inv = 1.f / l_s[rb + ii];
        *(float4*)(ybase + (size_t)(rb + ii) * (H_ * D_) + cb) =
            make_float4(o[ii][0] * inv, o[ii][1] * inv, o[ii][2] * inv, o[ii][3] * inv);
        *(float4*)(ybase + (size_t)(rb + ii) * (H_ * D_) + 64 + cb) =
            make_float4(o[ii][4] * inv, o[ii][5] * inv, o[ii][6] * inv, o[ii][7] * inv);
    }
}

// ---------------- host launcher ----------------
extern "C" void kernel_launch(void* const* d_in, const int* in_sizes, int n_in,
                              void* d_out, int out_size)
{
    const float* x     = (const float*)d_in[0];
    const float* fcos  = (const float*)d_in[1];
    const float* fsin  = (const float*)d_in[2];
    const float* wq    = (const float*)d_in[3];
    const float* wkv   = (const float*)d_in[4];
    const float* wk_up = (const float*)d_in[5];
    const float* wv_up = (const float*)d_in[6];
    const float* wo    = (const float*)d_in[7];
    float* out = (float*)d_out;

    float *pq, *plat, *pk, *pv, *py;
    __nv_bfloat16 *xhi, *xlo, *lhi, *llo;
    __nv_bfloat16 *wqhi, *wqlo, *wkvhi, *wkvlo, *wkuhi, *wkulo, *wvuhi, *wvulo, *wohi, *wolo;
    cudaGetSymbolAddress((void**)&pq,    g_q);
    cudaGetSymbolAddress((void**)&plat,  g_lat);
    cudaGetSymbolAddress((void**)&pk,    g_k);
    cudaGetSymbolAddress((void**)&pv,    g_v);
    cudaGetSymbolAddress((void**)&py,    g_y);
    cudaGetSymbolAddress((void**)&xhi,   g_xhi);
    cudaGetSymbolAddress((void**)&xlo,   g_xlo);
    cudaGetSymbolAddress((void**)&lhi,   g_lhi);
    cudaGetSymbolAddress((void**)&llo,   g_llo);
    cudaGetSymbolAddress((void**)&wqhi,  g_wqhi);
    cudaGetSymbolAddress((void**)&wqlo,  g_wqlo);
    cudaGetSymbolAddress((void**)&wkvhi, g_wkvhi);
    cudaGetSymbolAddress((void**)&wkvlo, g_wkvlo);
    cudaGetSymbolAddress((void**)&wkuhi, g_wkuhi);
    cudaGetSymbolAddress((void**)&wkulo, g_wkulo);
    cudaGetSymbolAddress((void**)&wvuhi, g_wvuhi);
    cudaGetSymbolAddress((void**)&wvulo, g_wvulo);
    cudaGetSymbolAddress((void**)&wohi,  g_wohi);
    cudaGetSymbolAddress((void**)&wolo,  g_wolo);

    cudaFuncSetAttribute(attn_kernel,
                         cudaFuncAttributeMaxDynamicSharedMemorySize, ATTN_SMEM_BYTES);
    cudaFuncSetAttribute(gemm_bf16x3,
                         cudaFuncAttributeMaxDynamicSharedMemorySize, GM_SMEM);

    cvt_split<<<(BT_*C_/4 + 255)/256, 256>>>(x, xhi, xlo, BT_*C_/4);
    cvt_split<<<(H_*D_*C_/4 + 255)/256, 256>>>(wq, wqhi, wqlo, H_*D_*C_/4);
    cvt_split<<<(L_*C_/4 + 255)/256, 256>>>(wkv, wkvhi, wkvlo, L_*C_/4);
    cvt_split<<<(D_*L_/4 + 255)/256, 256>>>(wk_up, wkuhi, wkulo, D_*L_/4);
    cvt_split<<<(D_*L_/4 + 255)/256, 256>>>(wv_up, wvuhi, wvulo, D_*L_/4);
    cvt_split<<<(C_*H_*D_/4 + 255)/256, 256>>>(wo, wohi, wolo, C_*H_*D_/4);

    gemm_bf16x3<<<dim3((H_*D_)/128, BT_/128), 256, GM_SMEM>>>(
        xhi, xlo, wqhi, wqlo, pq, H_*D_, C_);
    gemm_bf16x3<<<dim3(L_/128, BT_/128), 256, GM_SMEM>>>(
        xhi, xlo, wkvhi, wkvlo, plat, L_, C_);
    cvt_split<<<(BT_*L_/4 + 255)/256, 256>>>(plat, lhi, llo, BT_*L_/4);
    gemm_bf16x3<<<dim3(D_/128, BT_/128), 256, GM_SMEM>>>(
        lhi, llo, wkuhi, wkulo, pk, D_, L_);
    gemm_bf16x3<<<dim3(D_/128, BT_/128), 256, GM_SMEM>>>(
        lhi, llo, wvuhi, wvulo, pv, D_, L_);
    rope_q_kernel<<<(BT_*H_*64)/256, 256>>>(pq, fcos, fsin);
    rope_k_kernel<<<(BT_*64)/256, 256>>>(pk, fcos, fsin);
    attn_kernel<<<dim3(T_/BR, H_, B_), 256, ATTN_SMEM_BYTES>>>(pq, pk, pv, py);
    cvt_split<<<(BT_*H_*D_/4 + 255)/256, 256>>>(py, xhi, xlo, BT_*H_*D_/4);
    gemm_bf16x3<<<dim3(C_/128, BT_/128), 256, GM_SMEM>>>(
        xhi, xlo, wohi, wolo, out, C_, H_*D_);
}

// round 8
// speedup vs baseline: 2.8649x; 1.8065x over previous
#include <cuda_runtime.h>
#include <cuda_bf16.h>
#include <math.h>
#include <stdint.h>

#define B_ 4
#define T_ 2048
#define C_ 2048
#define H_ 16
#define D_ 128
#define L_ 512
#define BT_ (B_*T_)

// ---------------- scratch ----------------
__device__ float g_q[(size_t)BT_ * H_ * D_];
__device__ float g_lat[(size_t)BT_ * L_];
__device__ float g_k[(size_t)BT_ * D_];
__device__ float g_v[(size_t)BT_ * D_];

__device__ __nv_bfloat16 g_xhi[(size_t)BT_ * C_];   // x splits -> q splits -> y splits
__device__ __nv_bfloat16 g_xlo[(size_t)BT_ * C_];
__device__ __nv_bfloat16 g_lhi[(size_t)BT_ * L_];
__device__ __nv_bfloat16 g_llo[(size_t)BT_ * L_];
__device__ __nv_bfloat16 g_khi[(size_t)BT_ * D_], g_klo[(size_t)BT_ * D_];
__device__ __nv_bfloat16 g_vhi[(size_t)BT_ * D_], g_vlo[(size_t)BT_ * D_];
__device__ __nv_bfloat16 g_wqhi[(size_t)H_*D_*C_], g_wqlo[(size_t)H_*D_*C_];
__device__ __nv_bfloat16 g_wkvhi[(size_t)L_*C_],   g_wkvlo[(size_t)L_*C_];
__device__ __nv_bfloat16 g_wkuhi[(size_t)D_*L_],   g_wkulo[(size_t)D_*L_];
__device__ __nv_bfloat16 g_wvuhi[(size_t)D_*L_],   g_wvulo[(size_t)D_*L_];
__device__ __nv_bfloat16 g_wohi[(size_t)C_*H_*D_], g_wolo[(size_t)C_*H_*D_];

// ---------------- helpers ----------------
__device__ __forceinline__ uint32_t smem_u32(const void* p) {
    uint32_t a;
    asm("{ .reg .u64 t; cvta.to.shared.u64 t, %1; cvt.u32.u64 %0, t; }"
        : "=r"(a) : "l"(p));
    return a;
}
__device__ __forceinline__ void cp_async16(uint32_t dst, const void* src) {
    asm volatile("cp.async.cg.shared.global [%0], [%1], 16;"
                 :: "r"(dst), "l"(src) : "memory");
}
#define CP_COMMIT() asm volatile("cp.async.commit_group;" ::: "memory")
#define CP_WAIT1()  asm volatile("cp.async.wait_group 1;" ::: "memory")
#define CP_WAIT0()  asm volatile("cp.async.wait_group 0;" ::: "memory")

__device__ __forceinline__ void ldm_x4(uint32_t& r0, uint32_t& r1,
                                       uint32_t& r2, uint32_t& r3, uint32_t a) {
    asm volatile("ldmatrix.sync.aligned.m8n8.x4.shared.b16 {%0,%1,%2,%3}, [%4];"
                 : "=r"(r0), "=r"(r1), "=r"(r2), "=r"(r3) : "r"(a));
}
__device__ __forceinline__ void ldm_x4_t(uint32_t& r0, uint32_t& r1,
                                         uint32_t& r2, uint32_t& r3, uint32_t a) {
    asm volatile("ldmatrix.sync.aligned.m8n8.x4.trans.shared.b16 {%0,%1,%2,%3}, [%4];"
                 : "=r"(r0), "=r"(r1), "=r"(r2), "=r"(r3) : "r"(a));
}
__device__ __forceinline__ void mma16816(float* d, const uint32_t* a,
                                         uint32_t b0, uint32_t b1) {
    asm volatile(
        "mma.sync.aligned.m16n8k16.row.col.f32.bf16.bf16.f32 "
        "{%0,%1,%2,%3}, {%4,%5,%6,%7}, {%8,%9}, {%0,%1,%2,%3};"
        : "+f"(d[0]), "+f"(d[1]), "+f"(d[2]), "+f"(d[3])
        : "r"(a[0]), "r"(a[1]), "r"(a[2]), "r"(a[3]), "r"(b0), "r"(b1));
}
// pack two floats (even-k elem, odd-k elem) into one bf16x2 reg
__device__ __forceinline__ uint32_t pack_bf2(float lo, float hi) {
    uint32_t r;
    asm("cvt.rn.bf16x2.f32 %0, %1, %2;" : "=r"(r) : "f"(hi), "f"(lo));
    return r;
}

// ---------------- fp32 -> (hi,lo) bf16 split ----------------
__global__ void cvt_split(const float* __restrict__ s,
                          __nv_bfloat16* __restrict__ hi,
                          __nv_bfloat16* __restrict__ lo, int n4)
{
    int i = blockIdx.x * blockDim.x + threadIdx.x;
    if (i >= n4) return;
    float4 v = *(const float4*)(s + (size_t)i * 4);
    __nv_bfloat16 h0 = __float2bfloat16(v.x);
    __nv_bfloat16 h1 = __float2bfloat16(v.y);
    __nv_bfloat16 h2 = __float2bfloat16(v.z);
    __nv_bfloat16 h3 = __float2bfloat16(v.w);
    __nv_bfloat16 l0 = __float2bfloat16(v.x - __bfloat162float(h0));
    __nv_bfloat16 l1 = __float2bfloat16(v.y - __bfloat162float(h1));
    __nv_bfloat16 l2 = __float2bfloat16(v.z - __bfloat162float(h2));
    __nv_bfloat16 l3 = __float2bfloat16(v.w - __bfloat162float(h3));
    *(__nv_bfloat162*)(hi + (size_t)i * 4)     = __nv_bfloat162(h0, h1);
    *(__nv_bfloat162*)(hi + (size_t)i * 4 + 2) = __nv_bfloat162(h2, h3);
    *(__nv_bfloat162*)(lo + (size_t)i * 4)     = __nv_bfloat162(l0, l1);
    *(__nv_bfloat162*)(lo + (size_t)i * 4 + 2) = __nv_bfloat162(l2, l3);
}

// ---------------- mma.sync GEMM: C = A*B^T, 3-term bf16 split ----------------
#define GBK 32
#define GSTG 3
#define GTB 8192
#define GM_SMEM (2 * GSTG * GTB)

__global__ __launch_bounds__(256, 2) void gemm_bf16x3(
    const __nv_bfloat16* __restrict__ Ahi, const __nv_bfloat16* __restrict__ Alo,
    const __nv_bfloat16* __restrict__ Bhi, const __nv_bfloat16* __restrict__ Blo,
    float* __restrict__ Cm, int N, int K)
{
    extern __shared__ char smraw[];
    const uint32_t sA = smem_u32(smraw);
    const uint32_t sB = sA + GSTG * GTB;

    const int tid  = threadIdx.x;
    const int wid  = tid >> 5;
    const int lane = tid & 31;
    const int wm = wid >> 2;
    const int wn = wid & 3;
    const int n0 = blockIdx.x * 128;
    const int m0 = blockIdx.y * 128;

    const int KB = K / GBK;
    const int total = 3 * KB;

    float acc[4][4][4];
#pragma unroll
    for (int i = 0; i < 4; i++)
#pragma unroll
        for (int j = 0; j < 4; j++)
#pragma unroll
            for (int u = 0; u < 4; u++) acc[i][j][u] = 0.f;

    auto load_stage = [&](int j, int s) {
        const int p  = j / KB;
        const int kc = j - p * KB;
        const __nv_bfloat16* A  = (p == 2) ? Alo : Ahi;
        const __nv_bfloat16* Bp = (p == 1) ? Blo : Bhi;
        const uint32_t as = sA + (uint32_t)s * GTB;
        const uint32_t bs = sB + (uint32_t)s * GTB;
#pragma unroll
        for (int i = 0; i < 2; i++) {
            int ch  = tid + i * 256;
            int row = ch >> 2;
            int c   = ch & 3;
            int csw = c ^ ((row >> 1) & 3);
            uint32_t off = (uint32_t)(row * 64 + csw * 16);
            cp_async16(as + off, A  + (size_t)(m0 + row) * K + kc * GBK + c * 8);
            cp_async16(bs + off, Bp + (size_t)(n0 + row) * K + kc * GBK + c * 8);
        }
    };

    load_stage(0, 0); CP_COMMIT();
    load_stage(1, 1); CP_COMMIT();

    for (int j = 0; j < total; j++) {
        const int s = j % GSTG;
        CP_WAIT1();
        __syncthreads();
        if (j + 2 < total) load_stage(j + 2, (j + 2) % GSTG);
        CP_COMMIT();

        const uint32_t as = sA + (uint32_t)s * GTB;
        const uint32_t bs = sB + (uint32_t)s * GTB;
#pragma unroll
        for (int kk = 0; kk < 2; kk++) {
            uint32_t a[4][4], b[2][4];
#pragma unroll
            for (int mt = 0; mt < 4; mt++) {
                int row = wm * 64 + mt * 16 + (lane & 15);
                int cc  = kk * 2 + (lane >> 4);
                int csw = cc ^ ((row >> 1) & 3);
                ldm_x4(a[mt][0], a[mt][1], a[mt][2], a[mt][3],
                       as + (uint32_t)(row * 64 + csw * 16));
            }
#pragma unroll
            for (int np = 0; np < 2; np++) {
                int row = wn * 32 + np * 16 + (lane & 15);
                int cc  = kk * 2 + (lane >> 4);
                int csw = cc ^ ((row >> 1) & 3);
                ldm_x4(b[np][0], b[np][1], b[np][2], b[np][3],
                       bs + (uint32_t)(row * 64 + csw * 16));
            }
#pragma unroll
            for (int mt = 0; mt < 4; mt++)
#pragma unroll
                for (int nt = 0; nt < 4; nt++)
                    mma16816(acc[mt][nt], a[mt],
                             b[nt >> 1][nt & 1], b[nt >> 1][(nt & 1) + 2]);
        }
        __syncthreads();
    }

    const int r0g = m0 + wm * 64 + (lane >> 2);
    const int c0g = n0 + wn * 32 + (lane & 3) * 2;
#pragma unroll
    for (int mt = 0; mt < 4; mt++)
#pragma unroll
        for (int nt = 0; nt < 4; nt++) {
            float* p0 = Cm + (size_t)(r0g + mt * 16) * N + c0g + nt * 8;
            *(float2*)p0                    = make_float2(acc[mt][nt][0], acc[mt][nt][1]);
            *(float2*)(p0 + (size_t)8 * N)  = make_float2(acc[mt][nt][2], acc[mt][nt][3]);
        }
}

// ---------------- fused RoPE + hi/lo split ----------------
__global__ void rope_split_q(const float* __restrict__ q,
                             const float* __restrict__ cs, const float* __restrict__ sn,
                             __nv_bfloat16* __restrict__ hi, __nv_bfloat16* __restrict__ lo)
{
    int idx = blockIdx.x * blockDim.x + threadIdx.x;   // B*T*H*64 pairs
    int j = idx & 63;
    int t = (idx >> 10) & (T_ - 1);
    float c = cs[t * 64 + j];
    float s = sn[t * 64 + j];
    float2 v = *(const float2*)(q + (size_t)idx * 2);
    float o0 = v.x * c - v.y * s;
    float o1 = v.x * s + v.y * c;
    __nv_bfloat16 h0 = __float2bfloat16(o0), h1 = __float2bfloat16(o1);
    *(__nv_bfloat162*)(hi + (size_t)idx * 2) = __nv_bfloat162(h0, h1);
    *(__nv_bfloat162*)(lo + (size_t)idx * 2) = __nv_bfloat162(
        __float2bfloat16(o0 - __bfloat162float(h0)),
        __float2bfloat16(o1 - __bfloat162float(h1)));
}
__global__ void rope_split_k(const float* __restrict__ k,
                             const float* __restrict__ cs, const float* __restrict__ sn,
                             __nv_bfloat16* __restrict__ hi, __nv_bfloat16* __restrict__ lo)
{
    int idx = blockIdx.x * blockDim.x + threadIdx.x;   // B*T*64 pairs
    int j = idx & 63;
    int t = (idx >> 6) & (T_ - 1);
    float c = cs[t * 64 + j];
    float s = sn[t * 64 + j];
    float2 v = *(const float2*)(k + (size_t)idx * 2);
    float o0 = v.x * c - v.y * s;
    float o1 = v.x * s + v.y * c;
    __nv_bfloat16 h0 = __float2bfloat16(o0), h1 = __float2bfloat16(o1);
    *(__nv_bfloat162*)(hi + (size_t)idx * 2) = __nv_bfloat162(h0, h1);
    *(__nv_bfloat162*)(lo + (size_t)idx * 2) = __nv_bfloat162(
        __float2bfloat16(o0 - __bfloat162float(h0)),
        __float2bfloat16(o1 - __bfloat162float(h1)));
}

// ---------------- mma.sync flash attention ----------------
// BR=128 q rows, BC=64 kv cols/iter, 8 warps x 16 rows. Writes y as bf16 hi/lo.
#define AST 136                       // padded row stride (bf16 elems)
#define QT_B (128 * AST * 2)          // 34816 B per Q tensor
#define KT_B (64 * AST * 2)           // 17408 B per K/V tensor
#define STG_B (4 * KT_B)              // khi,klo,vhi,vlo
#define ATT_SMEM (2 * QT_B + 2 * STG_B)   // 208896

__global__ __launch_bounds__(256, 1) void attn_mma(
    const __nv_bfloat16* __restrict__ qhi, const __nv_bfloat16* __restrict__ qlo,
    const __nv_bfloat16* __restrict__ khi, const __nv_bfloat16* __restrict__ klo,
    const __nv_bfloat16* __restrict__ vhi, const __nv_bfloat16* __restrict__ vlo,
    __nv_bfloat16* __restrict__ yhi, __nv_bfloat16* __restrict__ ylo)
{
    extern __shared__ char smraw[];
    const uint32_t sQhi = smem_u32(smraw);
    const uint32_t sQlo = sQhi + QT_B;
    const uint32_t sStg = sQlo + QT_B;

    const int tid  = threadIdx.x;
    const int wid  = tid >> 5;
    const int lane = tid & 31;
    const int qt = (T_ / 128 - 1) - blockIdx.x;   // longest work first
    const int h  = blockIdx.y, b = blockIdx.z;
    const int t0 = qt * 128;
    const int jmax = 2 * qt + 1;
    const float scale = 0.08838834764831845f;

    // ---- Q load (once) ----
    {
        const size_t qb = (((size_t)b * T_ + t0) * H_ + h) * D_;
#pragma unroll
        for (int i = 0; i < 8; i++) {
            int ch  = tid + i * 256;          // 2048 chunks
            int row = ch >> 4;
            int c16 = ch & 15;
            uint32_t doff = (uint32_t)(row * AST + c16 * 8) * 2;
            size_t   soff = qb + (size_t)row * (H_ * D_) + c16 * 8;
            cp_async16(sQhi + doff, qhi + soff);
            cp_async16(sQlo + doff, qlo + soff);
        }
    }
    auto load_stage = [&](int j, int s) {
        const uint32_t sb = sStg + (uint32_t)s * STG_B;
        const size_t   gb = ((size_t)b * T_ + j * 64) * D_;
#pragma unroll
        for (int i = 0; i < 4; i++) {
            int ch  = tid + i * 256;          // 1024 chunks per tensor
            int row = ch >> 4;
            int c16 = ch & 15;
            uint32_t doff = (uint32_t)(row * AST + c16 * 8) * 2;
            size_t   soff = gb + (size_t)row * D_ + c16 * 8;
            cp_async16(sb + 0 * KT_B + doff, khi + soff);
            cp_async16(sb + 1 * KT_B + doff, klo + soff);
            cp_async16(sb + 2 * KT_B + doff, vhi + soff);
            cp_async16(sb + 3 * KT_B + doff, vlo + soff);
        }
    };
    load_stage(0, 0); CP_COMMIT();
    if (jmax >= 1) { load_stage(1, 1); CP_COMMIT(); }

    float m0 = -3.0e38f, m1 = -3.0e38f, l0 = 0.f, l1 = 0.f;
    float yacc[16][4];
#pragma unroll
    for (int nt = 0; nt < 16; nt++)
#pragma unroll
        for (int u = 0; u < 4; u++) yacc[nt][u] = 0.f;

    const int rloc = wid * 16 + (lane >> 2);   // local row of regs 0,1 (row+8 for 2,3)

    for (int j = 0; j <= jmax; j++) {
        const int s = j & 1;
        if (j < jmax) { CP_WAIT1(); } else { CP_WAIT0(); }
        __syncthreads();
        const uint32_t sK0 = sStg + (uint32_t)s * STG_B;
        const uint32_t sK1 = sK0 + KT_B;
        const uint32_t sV0 = sK0 + 2 * KT_B;
        const uint32_t sV1 = sK0 + 3 * KT_B;

        // ---- S = Q K^T (3-pass split) ----
        float sacc[8][4];
#pragma unroll
        for (int nt = 0; nt < 8; nt++)
#pragma unroll
            for (int u = 0; u < 4; u++) sacc[nt][u] = 0.f;

#pragma unroll
        for (int pass = 0; pass < 3; pass++) {
            const uint32_t aB = (pass == 2) ? sQlo : sQhi;
            const uint32_t bB = (pass == 1) ? sK1 : sK0;
#pragma unroll
            for (int kk = 0; kk < 8; kk++) {
                uint32_t a[4], bb[4][4];
                {
                    int row = wid * 16 + (lane & 15);
                    int col = kk * 16 + (lane >> 4) * 8;
                    ldm_x4(a[0], a[1], a[2], a[3],
                           aB + (uint32_t)(row * AST + col) * 2);
                }
#pragma unroll
                for (int nt2 = 0; nt2 < 4; nt2++) {
                    int row = nt2 * 16 + (lane & 15);
                    int col = kk * 16 + (lane >> 4) * 8;
                    ldm_x4(bb[nt2][0], bb[nt2][1], bb[nt2][2], bb[nt2][3],
                           bB + (uint32_t)(row * AST + col) * 2);
                }
#pragma unroll
                for (int nt = 0; nt < 8; nt++)
                    mma16816(sacc[nt], a,
                             bb[nt >> 1][nt & 1], bb[nt >> 1][(nt & 1) + 2]);
            }
        }

        // ---- scale + causal mask ----
        const bool need_mask = (j >= jmax - 1);
#pragma unroll
        for (int nt = 0; nt < 8; nt++)
#pragma unroll
            for (int u = 0; u < 4; u++) {
                float v = sacc[nt][u] * scale;
                if (need_mask) {
                    int rg = t0 + rloc + (u >> 1) * 8;
                    int cg = j * 64 + nt * 8 + (lane & 3) * 2 + (u & 1);
                    if (cg > rg) v = -1.0e30f;
                }
                sacc[nt][u] = v;
            }

        // ---- online softmax ----
        float rx0 = -3.0e38f, rx1 = -3.0e38f;
#pragma unroll
        for (int nt = 0; nt < 8; nt++) {
            rx0 = fmaxf(rx0, fmaxf(sacc[nt][0], sacc[nt][1]));
            rx1 = fmaxf(rx1, fmaxf(sacc[nt][2], sacc[nt][3]));
        }
        rx0 = fmaxf(rx0, __shfl_xor_sync(0xffffffffu, rx0, 1));
        rx0 = fmaxf(rx0, __shfl_xor_sync(0xffffffffu, rx0, 2));
        rx1 = fmaxf(rx1, __shfl_xor_sync(0xffffffffu, rx1, 1));
        rx1 = fmaxf(rx1, __shfl_xor_sync(0xffffffffu, rx1, 2));
        float mn0 = fmaxf(m0, rx0), mn1 = fmaxf(m1, rx1);
        float sc0 = __expf(m0 - mn0), sc1 = __expf(m1 - mn1);
        m0 = mn0; m1 = mn1;

        float rs0 = 0.f, rs1 = 0.f;
#pragma unroll
        for (int nt = 0; nt < 8; nt++) {
            sacc[nt][0] = __expf(sacc[nt][0] - mn0);
            sacc[nt][1] = __expf(sacc[nt][1] - mn0);
            sacc[nt][2] = __expf(sacc[nt][2] - mn1);
            sacc[nt][3] = __expf(sacc[nt][3] - mn1);
            rs0 += sacc[nt][0] + sacc[nt][1];
            rs1 += sacc[nt][2] + sacc[nt][3];
        }
        rs0 += __shfl_xor_sync(0xffffffffu, rs0, 1);
        rs0 += __shfl_xor_sync(0xffffffffu, rs0, 2);
        rs1 += __shfl_xor_sync(0xffffffffu, rs1, 1);
        rs1 += __shfl_xor_sync(0xffffffffu, rs1, 2);
        l0 = l0 * sc0 + rs0;
        l1 = l1 * sc1 + rs1;

#pragma unroll
        for (int nt = 0; nt < 16; nt++) {
            yacc[nt][0] *= sc0; yacc[nt][1] *= sc0;
            yacc[nt][2] *= sc1; yacc[nt][3] *= sc1;
        }

        // ---- P hi/lo a-fragments from registers ----
        uint32_t phiA[4][4], ploA[4][4];
#pragma unroll
        for (int kk2 = 0; kk2 < 4; kk2++) {
            const int ta = 2 * kk2, tb2 = 2 * kk2 + 1;
            float ph[8], pl[8];
            const float* src[2] = { sacc[ta], sacc[tb2] };
#pragma unroll
            for (int q2 = 0; q2 < 2; q2++)
#pragma unroll
                for (int u = 0; u < 4; u++) {
                    float p = src[q2][u];
                    __nv_bfloat16 hh = __float2bfloat16(p);
                    ph[q2 * 4 + u] = __bfloat162float(hh);
                    pl[q2 * 4 + u] = p - ph[q2 * 4 + u];
                }
            phiA[kk2][0] = pack_bf2(ph[0], ph[1]);
            phiA[kk2][1] = pack_bf2(ph[2], ph[3]);
            phiA[kk2][2] = pack_bf2(ph[4], ph[5]);
            phiA[kk2][3] = pack_bf2(ph[6], ph[7]);
            ploA[kk2][0] = pack_bf2(pl[0], pl[1]);
            ploA[kk2][1] = pack_bf2(pl[2], pl[3]);
            ploA[kk2][2] = pack_bf2(pl[4], pl[5]);
            ploA[kk2][3] = pack_bf2(pl[6], pl[7]);
        }

        // ---- Y += P V (phi*vhi + plo*vhi + phi*vlo) ----
#pragma unroll
        for (int kk2 = 0; kk2 < 4; kk2++) {
            uint32_t vb[8][4];
#pragma unroll
            for (int nt2 = 0; nt2 < 8; nt2++) {
                int row = kk2 * 16 + (lane & 15);
                int col = nt2 * 16 + (lane >> 4) * 8;
                ldm_x4_t(vb[nt2][0], vb[nt2][1], vb[nt2][2], vb[nt2][3],
                         sV0 + (uint32_t)(row * AST + col) * 2);
            }
#pragma unroll
            for (int nt = 0; nt < 16; nt++)
                mma16816(yacc[nt], phiA[kk2],
                         vb[nt >> 1][(nt & 1) * 2], vb[nt >> 1][(nt & 1) * 2 + 1]);
#pragma unroll
            for (int nt = 0; nt < 16; nt++)
                mma16816(yacc[nt], ploA[kk2],
                         vb[nt >> 1][(nt & 1) * 2], vb[nt >> 1][(nt & 1) * 2 + 1]);
#pragma unroll
            for (int nt2 = 0; nt2 < 8; nt2++) {
                int row = kk2 * 16 + (lane & 15);
                int col = nt2 * 16 + (lane >> 4) * 8;
                ldm_x4_t(vb[nt2][0], vb[nt2][1], vb[nt2][2], vb[nt2][3],
                         sV1 + (uint32_t)(row * AST + col) * 2);
            }
#pragma unroll
            for (int nt = 0; nt < 16; nt++)
                mma16816(yacc[nt], phiA[kk2],
                         vb[nt >> 1][(nt & 1) * 2], vb[nt >> 1][(nt & 1) * 2 + 1]);
        }

        __syncthreads();
        if (j + 2 <= jmax) { load_stage(j + 2, s); CP_COMMIT(); }
    }

    // ---- epilogue: y/l, split to bf16 hi/lo, store ----
    const float inv0 = 1.f / l0, inv1 = 1.f / l1;
#pragma unroll
    for (int half = 0; half < 2; half++) {
        const int rg = t0 + rloc + half * 8;
        const float inv = half ? inv1 : inv0;
        __nv_bfloat16* ph = yhi + (((size_t)b * T_ + rg) * H_ + h) * D_;
        __nv_bfloat16* pl = ylo + (((size_t)b * T_ + rg) * H_ + h) * D_;
#pragma unroll
        for (int nt = 0; nt < 16; nt++) {
            int cg = nt * 8 + (lane & 3) * 2;
            float v0 = yacc[nt][half * 2]     * inv;
            float v1 = yacc[nt][half * 2 + 1] * inv;
            __nv_bfloat16 h0 = __float2bfloat16(v0), h1 = __float2bfloat16(v1);
            *(__nv_bfloat162*)(ph + cg) = __nv_bfloat162(h0, h1);
            *(__nv_bfloat162*)(pl + cg) = __nv_bfloat162(
                __float2bfloat16(v0 - __bfloat162float(h0)),
                __float2bfloat16(v1 - __bfloat162float(h1)));
        }
    }
}

// ---------------- host launcher ----------------
extern "C" void kernel_launch(void* const* d_in, const int* in_sizes, int n_in,
                              void* d_out, int out_size)
{
    const float* x     = (const float*)d_in[0];
    const float* fcos  = (const float*)d_in[1];
    const float* fsin  = (const float*)d_in[2];
    const float* wq    = (const float*)d_in[3];
    const float* wkv   = (const float*)d_in[4];
    const float* wk_up = (const float*)d_in[5];
    const float* wv_up = (const float*)d_in[6];
    const float* wo    = (const float*)d_in[7];
    float* out = (float*)d_out;

    float *pq, *plat, *pk, *pv;
    __nv_bfloat16 *xhi, *xlo, *lhi, *llo, *khi, *klo, *vhi, *vlo;
    __nv_bfloat16 *wqhi, *wqlo, *wkvhi, *wkvlo, *wkuhi, *wkulo, *wvuhi, *wvulo, *wohi, *wolo;
    cudaGetSymbolAddress((void**)&pq,    g_q);
    cudaGetSymbolAddress((void**)&plat,  g_lat);
    cudaGetSymbolAddress((void**)&pk,    g_k);
    cudaGetSymbolAddress((void**)&pv,    g_v);
    cudaGetSymbolAddress((void**)&xhi,   g_xhi);
    cudaGetSymbolAddress((void**)&xlo,   g_xlo);
    cudaGetSymbolAddress((void**)&lhi,   g_lhi);
    cudaGetSymbolAddress((void**)&llo,   g_llo);
    cudaGetSymbolAddress((void**)&khi,   g_khi);
    cudaGetSymbolAddress((void**)&klo,   g_klo);
    cudaGetSymbolAddress((void**)&vhi,   g_vhi);
    cudaGetSymbolAddress((void**)&vlo,   g_vlo);
    cudaGetSymbolAddress((void**)&wqhi,  g_wqhi);
    cudaGetSymbolAddress((void**)&wqlo,  g_wqlo);
    cudaGetSymbolAddress((void**)&wkvhi, g_wkvhi);
    cudaGetSymbolAddress((void**)&wkvlo, g_wkvlo);
    cudaGetSymbolAddress((void**)&wkuhi, g_wkuhi);
    cudaGetSymbolAddress((void**)&wkulo, g_wkulo);
    cudaGetSymbolAddress((void**)&wvuhi, g_wvuhi);
    cudaGetSymbolAddress((void**)&wvulo, g_wvulo);
    cudaGetSymbolAddress((void**)&wohi,  g_wohi);
    cudaGetSymbolAddress((void**)&wolo,  g_wolo);

    cudaFuncSetAttribute(gemm_bf16x3,
                         cudaFuncAttributeMaxDynamicSharedMemorySize, GM_SMEM);
    cudaFuncSetAttribute(attn_mma,
                         cudaFuncAttributeMaxDynamicSharedMemorySize, ATT_SMEM);

    cvt_split<<<(BT_*C_/4 + 255)/256, 256>>>(x, xhi, xlo, BT_*C_/4);
    cvt_split<<<(H_*D_*C_/4 + 255)/256, 256>>>(wq, wqhi, wqlo, H_*D_*C_/4);
    cvt_split<<<(L_*C_/4 + 255)/256, 256>>>(wkv, wkvhi, wkvlo, L_*C_/4);
    cvt_split<<<(D_*L_/4 + 255)/256, 256>>>(wk_up, wkuhi, wkulo, D_*L_/4);
    cvt_split<<<(D_*L_/4 + 255)/256, 256>>>(wv_up, wvuhi, wvulo, D_*L_/4);
    cvt_split<<<(C_*H_*D_/4 + 255)/256, 256>>>(wo, wohi, wolo, C_*H_*D_/4);

    gemm_bf16x3<<<dim3((H_*D_)/128, BT_/128), 256, GM_SMEM>>>(
        xhi, xlo, wqhi, wqlo, pq, H_*D_, C_);
    gemm_bf16x3<<<dim3(L_/128, BT_/128), 256, GM_SMEM>>>(
        xhi, xlo, wkvhi, wkvlo, plat, L_, C_);
    cvt_split<<<(BT_*L_/4 + 255)/256, 256>>>(plat, lhi, llo, BT_*L_/4);
    gemm_bf16x3<<<dim3(D_/128, BT_/128), 256, GM_SMEM>>>(
        lhi, llo, wkuhi, wkulo, pk, D_, L_);
    gemm_bf16x3<<<dim3(D_/128, BT_/128), 256, GM_SMEM>>>(
        lhi, llo, wvuhi, wvulo, pv, D_, L_);

    // RoPE + split (q splits overwrite x splits, which are dead now)
    rope_split_q<<<(BT_*H_*64)/256, 256>>>(pq, fcos, fsin, xhi, xlo);
    rope_split_k<<<(BT_*64)/256, 256>>>(pk, fcos, fsin, khi, klo);
    cvt_split<<<(BT_*D_/4 + 255)/256, 256>>>(pv, vhi, vlo, BT_*D_/4);

    // attention: reads q from xhi/xlo, writes y (bf16 hi/lo) back into xhi/xlo
    attn_mma<<<dim3(T_/128, H_, B_), 256, ATT_SMEM>>>(
        xhi, xlo, khi, klo, vhi, vlo, xhi, xlo);

    gemm_bf16x3<<<dim3(C_/128, BT_/128), 256, GM_SMEM>>>(
        xhi, xlo, wohi, wolo, out, C_, H_*D_);
}

// round 9
// speedup vs baseline: 4.5613x; 1.5921x over previous
#include <cuda_runtime.h>
#include <cuda_fp16.h>
#include <math.h>
#include <stdint.h>

#define B_ 4
#define T_ 2048
#define C_ 2048
#define H_ 16
#define D_ 128
#define L_ 512
#define BT_ (B_*T_)
#define NQL 2560                      // combined q(2048) + lat(512) output width
#define NKV 256                       // combined k(128) + v(128) output width

// ---------------- scratch ----------------
__device__ float g_qlat[(size_t)BT_ * NQL];     // 80 MB: q | lat
__device__ float g_kv[(size_t)BT_ * NKV];       // 8 MB: k | v

__device__ __half g_xhi[(size_t)BT_ * C_];      // x splits -> q splits -> y splits
__device__ __half g_xlo[(size_t)BT_ * C_];
__device__ __half g_lhi[(size_t)BT_ * L_];
__device__ __half g_llo[(size_t)BT_ * L_];
__device__ __half g_kh[(size_t)BT_ * D_];
__device__ __half g_vh[(size_t)BT_ * D_];
__device__ __half g_wqkvh[(size_t)NQL * C_];    // wq rows 0..2047, wkv rows 2048..2559
__device__ __half g_wuph[(size_t)NKV * L_];     // wku rows 0..127, wvu rows 128..255
__device__ __half g_woh[(size_t)C_ * H_ * D_];

// ---------------- helpers ----------------
__device__ __forceinline__ uint32_t smem_u32(const void* p) {
    uint32_t a;
    asm("{ .reg .u64 t; cvta.to.shared.u64 t, %1; cvt.u32.u64 %0, t; }"
        : "=r"(a) : "l"(p));
    return a;
}
__device__ __forceinline__ void cp_async16(uint32_t dst, const void* src) {
    asm volatile("cp.async.cg.shared.global [%0], [%1], 16;"
                 :: "r"(dst), "l"(src) : "memory");
}
#define CP_COMMIT() asm volatile("cp.async.commit_group;" ::: "memory")
#define CP_WAIT1()  asm volatile("cp.async.wait_group 1;" ::: "memory")
#define CP_WAIT0()  asm volatile("cp.async.wait_group 0;" ::: "memory")

__device__ __forceinline__ void ldm_x4(uint32_t& r0, uint32_t& r1,
                                       uint32_t& r2, uint32_t& r3, uint32_t a) {
    asm volatile("ldmatrix.sync.aligned.m8n8.x4.shared.b16 {%0,%1,%2,%3}, [%4];"
                 : "=r"(r0), "=r"(r1), "=r"(r2), "=r"(r3) : "r"(a));
}
__device__ __forceinline__ void ldm_x4_t(uint32_t& r0, uint32_t& r1,
                                         uint32_t& r2, uint32_t& r3, uint32_t a) {
    asm volatile("ldmatrix.sync.aligned.m8n8.x4.trans.shared.b16 {%0,%1,%2,%3}, [%4];"
                 : "=r"(r0), "=r"(r1), "=r"(r2), "=r"(r3) : "r"(a));
}
__device__ __forceinline__ void mma16816(float* d, const uint32_t* a,
                                         uint32_t b0, uint32_t b1) {
    asm volatile(
        "mma.sync.aligned.m16n8k16.row.col.f32.f16.f16.f32 "
        "{%0,%1,%2,%3}, {%4,%5,%6,%7}, {%8,%9}, {%0,%1,%2,%3};"
        : "+f"(d[0]), "+f"(d[1]), "+f"(d[2]), "+f"(d[3])
        : "r"(a[0]), "r"(a[1]), "r"(a[2]), "r"(a[3]), "r"(b0), "r"(b1));
}
// pack two floats (even-k, odd-k) into one f16x2 reg
__device__ __forceinline__ uint32_t pack_h2(float lo, float hi) {
    uint32_t r;
    asm("cvt.rn.f16x2.f32 %0, %1, %2;" : "=r"(r) : "f"(hi), "f"(lo));
    return r;
}

// ---------------- conversion kernels ----------------
__global__ void cvt_split_h(const float* __restrict__ s,
                            __half* __restrict__ hi, __half* __restrict__ lo, int n4)
{
    int i = blockIdx.x * blockDim.x + threadIdx.x;
    if (i >= n4) return;
    float4 v = *(const float4*)(s + (size_t)i * 4);
    __half h0 = __float2half_rn(v.x), h1 = __float2half_rn(v.y);
    __half h2 = __float2half_rn(v.z), h3 = __float2half_rn(v.w);
    *(__half2*)(hi + (size_t)i * 4)     = __halves2half2(h0, h1);
    *(__half2*)(hi + (size_t)i * 4 + 2) = __halves2half2(h2, h3);
    *(__half2*)(lo + (size_t)i * 4)     = __halves2half2(
        __float2half_rn(v.x - __half2float(h0)), __float2half_rn(v.y - __half2float(h1)));
    *(__half2*)(lo + (size_t)i * 4 + 2) = __halves2half2(
        __float2half_rn(v.z - __half2float(h2)), __float2half_rn(v.w - __half2float(h3)));
}
__global__ void cvt_h(const float* __restrict__ s, __half* __restrict__ d, int n4)
{
    int i = blockIdx.x * blockDim.x + threadIdx.x;
    if (i >= n4) return;
    float4 v = *(const float4*)(s + (size_t)i * 4);
    *(__half2*)(d + (size_t)i * 4)     = __halves2half2(__float2half_rn(v.x), __float2half_rn(v.y));
    *(__half2*)(d + (size_t)i * 4 + 2) = __halves2half2(__float2half_rn(v.z), __float2half_rn(v.w));
}
// lat (cols 2048..2559 of g_qlat) -> dense hi/lo
__global__ void lat_split(const float* __restrict__ src,
                          __half* __restrict__ hi, __half* __restrict__ lo)
{
    int i = blockIdx.x * blockDim.x + threadIdx.x;   // BT*128 float4s
    int r = i >> 7;
    int c = (i & 127) << 2;
    float4 v = *(const float4*)(src + (size_t)r * NQL + C_ + c);
    __half h0 = __float2half_rn(v.x), h1 = __float2half_rn(v.y);
    __half h2 = __float2half_rn(v.z), h3 = __float2half_rn(v.w);
    size_t o = (size_t)r * L_ + c;
    *(__half2*)(hi + o)     = __halves2half2(h0, h1);
    *(__half2*)(hi + o + 2) = __halves2half2(h2, h3);
    *(__half2*)(lo + o)     = __halves2half2(
        __float2half_rn(v.x - __half2float(h0)), __float2half_rn(v.y - __half2float(h1)));
    *(__half2*)(lo + o + 2) = __halves2half2(
        __float2half_rn(v.z - __half2float(h2)), __float2half_rn(v.w - __half2float(h3)));
}
// v (cols 128..255 of g_kv) -> dense fp16 (no split; B-side)
__global__ void v_cvt(const float* __restrict__ src, __half* __restrict__ vh)
{
    int i = blockIdx.x * blockDim.x + threadIdx.x;   // BT*32 float4s
    int r = i >> 5;
    int c = (i & 31) << 2;
    float4 v = *(const float4*)(src + (size_t)r * NKV + D_ + c);
    size_t o = (size_t)r * D_ + c;
    *(__half2*)(vh + o)     = __halves2half2(__float2half_rn(v.x), __float2half_rn(v.y));
    *(__half2*)(vh + o + 2) = __halves2half2(__float2half_rn(v.z), __float2half_rn(v.w));
}
// RoPE + split for q (A-side): reads q cols of g_qlat, writes dense hi/lo
__global__ void rope_split_q(const float* __restrict__ src,
                             const float* __restrict__ cs, const float* __restrict__ sn,
                             __half* __restrict__ hi, __half* __restrict__ lo)
{
    int idx = blockIdx.x * blockDim.x + threadIdx.x;   // BT*1024 pairs
    int p = idx & 1023;
    int r = idx >> 10;
    int j = p & 63;
    int t = r & (T_ - 1);
    float c = cs[t * 64 + j];
    float s = sn[t * 64 + j];
    float2 v = *(const float2*)(src + (size_t)r * NQL + p * 2);
    float o0 = v.x * c - v.y * s;
    float o1 = v.x * s + v.y * c;
    __half h0 = __float2half_rn(o0), h1 = __float2half_rn(o1);
    size_t o = (size_t)idx * 2;
    *(__half2*)(hi + o) = __halves2half2(h0, h1);
    *(__half2*)(lo + o) = __halves2half2(
        __float2half_rn(o0 - __half2float(h0)),
        __float2half_rn(o1 - __half2float(h1)));
}
// RoPE for k (B-side, fp16 only)
__global__ void rope_split_k(const float* __restrict__ src,
                             const float* __restrict__ cs, const float* __restrict__ sn,
                             __half* __restrict__ kh)
{
    int idx = blockIdx.x * blockDim.x + threadIdx.x;   // BT*64 pairs
    int p = idx & 63;
    int r = idx >> 6;
    int t = r & (T_ - 1);
    float c = cs[t * 64 + p];
    float s = sn[t * 64 + p];
    float2 v = *(const float2*)(src + (size_t)r * NKV + p * 2);
    float o0 = v.x * c - v.y * s;
    float o1 = v.x * s + v.y * c;
    *(__half2*)(kh + (size_t)idx * 2) =
        __halves2half2(__float2half_rn(o0), __float2half_rn(o1));
}

// ---------------- mma.sync GEMM: C = A*B^T, 2-pass fp16 split (A split, B single) ----------------
#define GBK 32
#define GSTG 3
#define GTB 8192
#define GM_SMEM (2 * GSTG * GTB)

__global__ __launch_bounds__(256, 2) void gemm_f16x2(
    const __half* __restrict__ Ahi, const __half* __restrict__ Alo,
    const __half* __restrict__ Bh, float* __restrict__ Cm, int N, int K)
{
    extern __shared__ char smraw[];
    const uint32_t sA = smem_u32(smraw);
    const uint32_t sB = sA + GSTG * GTB;

    const int tid  = threadIdx.x;
    const int wid  = tid >> 5;
    const int lane = tid & 31;
    const int wm = wid >> 2;
    const int wn = wid & 3;
    const int n0 = blockIdx.x * 128;
    const int m0 = blockIdx.y * 128;

    const int KB = K / GBK;
    const int total = 2 * KB;

    float acc[4][4][4];
#pragma unroll
    for (int i = 0; i < 4; i++)
#pragma unroll
        for (int j = 0; j < 4; j++)
#pragma unroll
            for (int u = 0; u < 4; u++) acc[i][j][u] = 0.f;

    auto load_stage = [&](int j, int s) {
        const int kc = (j >= KB) ? (j - KB) : j;
        const __half* A = (j >= KB) ? Alo : Ahi;
        const uint32_t as = sA + (uint32_t)s * GTB;
        const uint32_t bs = sB + (uint32_t)s * GTB;
#pragma unroll
        for (int i = 0; i < 2; i++) {
            int ch  = tid + i * 256;
            int row = ch >> 2;
            int c   = ch & 3;
            int csw = c ^ ((row >> 1) & 3);
            uint32_t off = (uint32_t)(row * 64 + csw * 16);
            cp_async16(as + off, A  + (size_t)(m0 + row) * K + kc * GBK + c * 8);
            cp_async16(bs + off, Bh + (size_t)(n0 + row) * K + kc * GBK + c * 8);
        }
    };

    load_stage(0, 0); CP_COMMIT();
    load_stage(1, 1); CP_COMMIT();

    for (int j = 0; j < total; j++) {
        const int s = j % GSTG;
        CP_WAIT1();
        __syncthreads();
        if (j + 2 < total) load_stage(j + 2, (j + 2) % GSTG);
        CP_COMMIT();

        const uint32_t as = sA + (uint32_t)s * GTB;
        const uint32_t bs = sB + (uint32_t)s * GTB;
#pragma unroll
        for (int kk = 0; kk < 2; kk++) {
            uint32_t a[4][4], b[2][4];
#pragma unroll
            for (int mt = 0; mt < 4; mt++) {
                int row = wm * 64 + mt * 16 + (lane & 15);
                int cc  = kk * 2 + (lane >> 4);
                int csw = cc ^ ((row >> 1) & 3);
                ldm_x4(a[mt][0], a[mt][1], a[mt][2], a[mt][3],
                       as + (uint32_t)(row * 64 + csw * 16));
            }
#pragma unroll
            for (int np = 0; np < 2; np++) {
                int row = wn * 32 + np * 16 + (lane & 15);
                int cc  = kk * 2 + (lane >> 4);
                int csw = cc ^ ((row >> 1) & 3);
                ldm_x4(b[np][0], b[np][1], b[np][2], b[np][3],
                       bs + (uint32_t)(row * 64 + csw * 16));
            }
#pragma unroll
            for (int mt = 0; mt < 4; mt++)
#pragma unroll
                for (int nt = 0; nt < 4; nt++)
                    mma16816(acc[mt][nt], a[mt],
                             b[nt >> 1][nt & 1], b[nt >> 1][(nt & 1) + 2]);
        }
        __syncthreads();
    }

    const int r0g = m0 + wm * 64 + (lane >> 2);
    const int c0g = n0 + wn * 32 + (lane & 3) * 2;
#pragma unroll
    for (int mt = 0; mt < 4; mt++)
#pragma unroll
        for (int nt = 0; nt < 4; nt++) {
            float* p0 = Cm + (size_t)(r0g + mt * 16) * N + c0g + nt * 8;
            *(float2*)p0                    = make_float2(acc[mt][nt][0], acc[mt][nt][1]);
            *(float2*)(p0 + (size_t)8 * N)  = make_float2(acc[mt][nt][2], acc[mt][nt][3]);
        }
}

// ---------------- mma.sync flash attention (fp16, 2-pass QK, 2-pass PV) ----------------
#define AST 136
#define QT_B (128 * AST * 2)          // 34816 B
#define KT_B (64 * AST * 2)           // 17408 B
#define STG_B (2 * KT_B)              // kh, vh
#define ATT_SMEM (2 * QT_B + 2 * STG_B)   // 139264

__global__ __launch_bounds__(256, 1) void attn_mma(
    const __half* __restrict__ qhi, const __half* __restrict__ qlo,
    const __half* __restrict__ kh, const __half* __restrict__ vh,
    __half* __restrict__ yhi, __half* __restrict__ ylo)
{
    extern __shared__ char smraw[];
    const uint32_t sQhi = smem_u32(smraw);
    const uint32_t sQlo = sQhi + QT_B;
    const uint32_t sStg = sQlo + QT_B;

    const int tid  = threadIdx.x;
    const int wid  = tid >> 5;
    const int lane = tid & 31;
    const int qt = (T_ / 128 - 1) - blockIdx.x;
    const int h  = blockIdx.y, b = blockIdx.z;
    const int t0 = qt * 128;
    const int jmax = 2 * qt + 1;
    const float scale = 0.08838834764831845f;

    {
        const size_t qb = (((size_t)b * T_ + t0) * H_ + h) * D_;
#pragma unroll
        for (int i = 0; i < 8; i++) {
            int ch  = tid + i * 256;
            int row = ch >> 4;
            int c16 = ch & 15;
            uint32_t doff = (uint32_t)(row * AST + c16 * 8) * 2;
            size_t   soff = qb + (size_t)row * (H_ * D_) + c16 * 8;
            cp_async16(sQhi + doff, qhi + soff);
            cp_async16(sQlo + doff, qlo + soff);
        }
    }
    auto load_stage = [&](int j, int s) {
        const uint32_t sb = sStg + (uint32_t)s * STG_B;
        const size_t   gb = ((size_t)b * T_ + j * 64) * D_;
#pragma unroll
        for (int i = 0; i < 4; i++) {
            int ch  = tid + i * 256;
            int row = ch >> 4;
            int c16 = ch & 15;
            uint32_t doff = (uint32_t)(row * AST + c16 * 8) * 2;
            size_t   soff = gb + (size_t)row * D_ + c16 * 8;
            cp_async16(sb + doff,        kh + soff);
            cp_async16(sb + KT_B + doff, vh + soff);
        }
    };
    load_stage(0, 0); CP_COMMIT();
    load_stage(1, 1); CP_COMMIT();

    float m0 = -3.0e38f, m1 = -3.0e38f, l0 = 0.f, l1 = 0.f;
    float yacc[16][4];
#pragma unroll
    for (int nt = 0; nt < 16; nt++)
#pragma unroll
        for (int u = 0; u < 4; u++) yacc[nt][u] = 0.f;

    const int rloc = wid * 16 + (lane >> 2);

    for (int j = 0; j <= jmax; j++) {
        const int s = j & 1;
        if (j < jmax) { CP_WAIT1(); } else { CP_WAIT0(); }
        __syncthreads();
        const uint32_t sKh = sStg + (uint32_t)s * STG_B;
        const uint32_t sVh = sKh + KT_B;

        // ---- S = Q K^T : both A passes share one K-fragment load ----
        float sacc[8][4];
#pragma unroll
        for (int nt = 0; nt < 8; nt++)
#pragma unroll
            for (int u = 0; u < 4; u++) sacc[nt][u] = 0.f;

#pragma unroll
        for (int kk = 0; kk < 8; kk++) {
            uint32_t ah[4], al[4], bb[4][4];
            {
                int row = wid * 16 + (lane & 15);
                int col = kk * 16 + (lane >> 4) * 8;
                uint32_t off = (uint32_t)(row * AST + col) * 2;
                ldm_x4(ah[0], ah[1], ah[2], ah[3], sQhi + off);
                ldm_x4(al[0], al[1], al[2], al[3], sQlo + off);
            }
#pragma unroll
            for (int nt2 = 0; nt2 < 4; nt2++) {
                int row = nt2 * 16 + (lane & 15);
                int col = kk * 16 + (lane >> 4) * 8;
                ldm_x4(bb[nt2][0], bb[nt2][1], bb[nt2][2], bb[nt2][3],
                       sKh + (uint32_t)(row * AST + col) * 2);
            }
#pragma unroll
            for (int nt = 0; nt < 8; nt++) {
                mma16816(sacc[nt], ah, bb[nt >> 1][nt & 1], bb[nt >> 1][(nt & 1) + 2]);
                mma16816(sacc[nt], al, bb[nt >> 1][nt & 1], bb[nt >> 1][(nt & 1) + 2]);
            }
        }

        // ---- scale + causal mask ----
        const bool need_mask = (j >= jmax - 1);
#pragma unroll
        for (int nt = 0; nt < 8; nt++)
#pragma unroll
            for (int u = 0; u < 4; u++) {
                float v = sacc[nt][u] * scale;
                if (need_mask) {
                    int rg = t0 + rloc + (u >> 1) * 8;
                    int cg = j * 64 + nt * 8 + (lane & 3) * 2 + (u & 1);
                    if (cg > rg) v = -1.0e30f;
                }
                sacc[nt][u] = v;
            }

        // ---- online softmax ----
        float rx0 = -3.0e38f, rx1 = -3.0e38f;
#pragma unroll
        for (int nt = 0; nt < 8; nt++) {
            rx0 = fmaxf(rx0, fmaxf(sacc[nt][0], sacc[nt][1]));
            rx1 = fmaxf(rx1, fmaxf(sacc[nt][2], sacc[nt][3]));
        }
        rx0 = fmaxf(rx0, __shfl_xor_sync(0xffffffffu, rx0, 1));
        rx0 = fmaxf(rx0, __shfl_xor_sync(0xffffffffu, rx0, 2));
        rx1 = fmaxf(rx1, __shfl_xor_sync(0xffffffffu, rx1, 1));
        rx1 = fmaxf(rx1, __shfl_xor_sync(0xffffffffu, rx1, 2));
        float mn0 = fmaxf(m0, rx0), mn1 = fmaxf(m1, rx1);
        float sc0 = __expf(m0 - mn0), sc1 = __expf(m1 - mn1);
        m0 = mn0; m1 = mn1;

        float rs0 = 0.f, rs1 = 0.f;
#pragma unroll
        for (int nt = 0; nt < 8; nt++) {
            sacc[nt][0] = __expf(sacc[nt][0] - mn0);
            sacc[nt][1] = __expf(sacc[nt][1] - mn0);
            sacc[nt][2] = __expf(sacc[nt][2] - mn1);
            sacc[nt][3] = __expf(sacc[nt][3] - mn1);
            rs0 += sacc[nt][0] + sacc[nt][1];
            rs1 += sacc[nt][2] + sacc[nt][3];
        }
        rs0 += __shfl_xor_sync(0xffffffffu, rs0, 1);
        rs0 += __shfl_xor_sync(0xffffffffu, rs0, 2);
        rs1 += __shfl_xor_sync(0xffffffffu, rs1, 1);
        rs1 += __shfl_xor_sync(0xffffffffu, rs1, 2);
        l0 = l0 * sc0 + rs0;
        l1 = l1 * sc1 + rs1;

#pragma unroll
        for (int nt = 0; nt < 16; nt++) {
            yacc[nt][0] *= sc0; yacc[nt][1] *= sc0;
            yacc[nt][2] *= sc1; yacc[nt][3] *= sc1;
        }

        // ---- P hi/lo a-fragments (fp16) ----
        uint32_t phiA[4][4], ploA[4][4];
#pragma unroll
        for (int kk2 = 0; kk2 < 4; kk2++) {
            const int ta = 2 * kk2, tb2 = 2 * kk2 + 1;
            float ph[8], pl[8];
            const float* src[2] = { sacc[ta], sacc[tb2] };
#pragma unroll
            for (int q2 = 0; q2 < 2; q2++)
#pragma unroll
                for (int u = 0; u < 4; u++) {
                    float p = src[q2][u];
                    __half hh = __float2half_rn(p);
                    ph[q2 * 4 + u] = __half2float(hh);
                    pl[q2 * 4 + u] = p - ph[q2 * 4 + u];
                }
            phiA[kk2][0] = pack_h2(ph[0], ph[1]);
            phiA[kk2][1] = pack_h2(ph[2], ph[3]);
            phiA[kk2][2] = pack_h2(ph[4], ph[5]);
            phiA[kk2][3] = pack_h2(ph[6], ph[7]);
            ploA[kk2][0] = pack_h2(pl[0], pl[1]);
            ploA[kk2][1] = pack_h2(pl[2], pl[3]);
            ploA[kk2][2] = pack_h2(pl[4], pl[5]);
            ploA[kk2][3] = pack_h2(pl[6], pl[7]);
        }

        // ---- Y += P V (phi*vh + plo*vh), V fragments loaded once ----
#pragma unroll
        for (int kk2 = 0; kk2 < 4; kk2++) {
            uint32_t vb[8][4];
#pragma unroll
            for (int nt2 = 0; nt2 < 8; nt2++) {
                int row = kk2 * 16 + (lane & 15);
                int col = nt2 * 16 + (lane >> 4) * 8;
                ldm_x4_t(vb[nt2][0], vb[nt2][1], vb[nt2][2], vb[nt2][3],
                         sVh + (uint32_t)(row * AST + col) * 2);
            }
#pragma unroll
            for (int nt = 0; nt < 16; nt++) {
                mma16816(yacc[nt], phiA[kk2],
                         vb[nt >> 1][(nt & 1) * 2], vb[nt >> 1][(nt & 1) * 2 + 1]);
                mma16816(yacc[nt], ploA[kk2],
                         vb[nt >> 1][(nt & 1) * 2], vb[nt >> 1][(nt & 1) * 2 + 1]);
            }
        }

        __syncthreads();
        if (j + 2 <= jmax) { load_stage(j + 2, s); CP_COMMIT(); }
    }

    // ---- epilogue: y/l, split to fp16 hi/lo ----
    const float inv0 = 1.f / l0, inv1 = 1.f / l1;
#pragma unroll
    for (int half = 0; half < 2; half++) {
        const int rg = t0 + rloc + half * 8;
        const float inv = half ? inv1 : inv0;
        __half* ph = yhi + (((size_t)b * T_ + rg) * H_ + h) * D_;
        __half* pl = ylo + (((size_t)b * T_ + rg) * H_ + h) * D_;
#pragma unroll
        for (int nt = 0; nt < 16; nt++) {
            int cg = nt * 8 + (lane & 3) * 2;
            float v0 = yacc[nt][half * 2]     * inv;
            float v1 = yacc[nt][half * 2 + 1] * inv;
            __half h0 = __float2half_rn(v0), h1 = __float2half_rn(v1);
            *(__half2*)(ph + cg) = __halves2half2(h0, h1);
            *(__half2*)(pl + cg) = __halves2half2(
                __float2half_rn(v0 - __half2float(h0)),
                __float2half_rn(v1 - __half2float(h1)));
        }
    }
}

// ---------------- host launcher ----------------
extern "C" void kernel_launch(void* const* d_in, const int* in_sizes, int n_in,
                              void* d_out, int out_size)
{
    const float* x     = (const float*)d_in[0];
    const float* fcos  = (const float*)d_in[1];
    const float* fsin  = (const float*)d_in[2];
    const float* wq    = (const float*)d_in[3];
    const float* wkv   = (const float*)d_in[4];
    const float* wk_up = (const float*)d_in[5];
    const float* wv_up = (const float*)d_in[6];
    const float* wo    = (const float*)d_in[7];
    float* out = (float*)d_out;

    float *pql, *pkv;
    __half *xhi, *xlo, *lhi, *llo, *kh, *vh, *wqkvh, *wuph, *woh;
    cudaGetSymbolAddress((void**)&pql,   g_qlat);
    cudaGetSymbolAddress((void**)&pkv,   g_kv);
    cudaGetSymbolAddress((void**)&xhi,   g_xhi);
    cudaGetSymbolAddress((void**)&xlo,   g_xlo);
    cudaGetSymbolAddress((void**)&lhi,   g_lhi);
    cudaGetSymbolAddress((void**)&llo,   g_llo);
    cudaGetSymbolAddress((void**)&kh,    g_kh);
    cudaGetSymbolAddress((void**)&vh,    g_vh);
    cudaGetSymbolAddress((void**)&wqkvh, g_wqkvh);
    cudaGetSymbolAddress((void**)&wuph,  g_wuph);
    cudaGetSymbolAddress((void**)&woh,   g_woh);

    cudaFuncSetAttribute(gemm_f16x2,
                         cudaFuncAttributeMaxDynamicSharedMemorySize, GM_SMEM);
    cudaFuncSetAttribute(attn_mma,
                         cudaFuncAttributeMaxDynamicSharedMemorySize, ATT_SMEM);

    // conversions
    cvt_split_h<<<(BT_*C_/4)/256, 256>>>(x, xhi, xlo, BT_*C_/4);
    cvt_h<<<(H_*D_*C_/4)/256, 256>>>(wq, wqkvh, H_*D_*C_/4);
    cvt_h<<<(L_*C_/4)/256, 256>>>(wkv, wqkvh + (size_t)H_*D_*C_, L_*C_/4);
    cvt_h<<<(D_*L_/4)/256, 256>>>(wk_up, wuph, D_*L_/4);
    cvt_h<<<(D_*L_/4)/256, 256>>>(wv_up, wuph + (size_t)D_*L_, D_*L_/4);
    cvt_h<<<(C_*H_*D_/4)/256, 256>>>(wo, woh, C_*H_*D_/4);

    // fused q+lat projection: [BT, 2560] = x @ [wq;wkv]^T
    gemm_f16x2<<<dim3(NQL/128, BT_/128), 256, GM_SMEM>>>(
        xhi, xlo, wqkvh, pql, NQL, C_);
    // split lat, fused k+v up-projection: [BT, 256] = lat @ [wku;wvu]^T
    lat_split<<<(BT_*L_/4)/256, 256>>>(pql, lhi, llo);
    gemm_f16x2<<<dim3(NKV/128, BT_/128), 256, GM_SMEM>>>(
        lhi, llo, wuph, pkv, NKV, L_);

    // RoPE + splits (q splits overwrite x splits)
    rope_split_q<<<(BT_*1024)/256, 256>>>(pql, fcos, fsin, xhi, xlo);
    rope_split_k<<<(BT_*64)/256, 256>>>(pkv, fcos, fsin, kh);
    v_cvt<<<(BT_*D_/4)/256, 256>>>(pkv, vh);

    // attention: y splits written back into xhi/xlo
    attn_mma<<<dim3(T_/128, H_, B_), 256, ATT_SMEM>>>(
        xhi, xlo, kh, vh, xhi, xlo);

    // output projection
    gemm_f16x2<<<dim3(C_/128, BT_/128), 256, GM_SMEM>>>(
        xhi, xlo, woh, out, C_, H_*D_);
}